// round 3
// baseline (speedup 1.0000x reference)
#include <cuda_runtime.h>

// Problem constants
#define Bc 16
#define Dc 64
#define Tc 8192
#define Kc 512
#define DT (Dc * Tc)        // 524288
#define BT (Bc * Tc)        // 131072
#define THREADS 256
#define NPAIR (Kc / 2)      // 256 codeword pairs
#define GRID 148            // persistent: 1 CTA/SM, grid-stride over tokens

// smem: pcb[256 pairs][64 d] as u64 {c_2p[d], c_2p+1[d]}  +  scn[512]
#define PCB_ULL (NPAIR * Dc)                  // 16384 u64 = 128 KB
#define SMEM_BYTES (PCB_ULL * 8 + Kc * 4)     // 133120 B

typedef unsigned long long ull;

__global__ __launch_bounds__(THREADS, 1)
void vq_kernel(const float* __restrict__ x,
               const float* __restrict__ cb,
               float* __restrict__ out,
               int write_second)
{
    extern __shared__ ull smem_u64[];
    ull* pcb = smem_u64;
    float* scn = (float*)(smem_u64 + PCB_ULL);

    const int tid = threadIdx.x;

    // ---- build pair-interleaved codebook: pcb[p*64+d] = {cb[2p][d], cb[2p+1][d]} ----
    for (int i = tid; i < PCB_ULL; i += THREADS) {
        const int p = i >> 6, d = i & 63;
        const float lo = cb[(2 * p) * Dc + d];
        const float hi = cb[(2 * p + 1) * Dc + d];
        ull v;
        asm("mov.b64 %0, {%1, %2};" : "=l"(v) : "f"(lo), "f"(hi));
        pcb[i] = v;
    }
    // ---- cn[k] = sum_d round(c_d*c_d), serial ascending add (match XLA square+reduce) ----
    for (int k = tid; k < Kc; k += THREADS) {
        float s = 0.f;
        #pragma unroll
        for (int d = 0; d < Dc; d++) {
            const float c = cb[k * Dc + d];
            s = __fadd_rn(s, __fmul_rn(c, c));
        }
        scn[k] = s;
    }
    __syncthreads();

    unsigned int pcb_addr;
    asm("{ .reg .u64 tt; cvta.to.shared.u64 tt, %1; cvt.u32.u64 %0, tt; }"
        : "=r"(pcb_addr) : "l"(pcb));

    // ---- persistent grid-stride over tokens (uniform per CTA: BT, stride mult. of 256) ----
    for (int token = blockIdx.x * THREADS + tid; token < BT;
         token += GRID * THREADS) {

        const int b = token >> 13;          // / Tc
        const int t = token & (Tc - 1);
        const float* xp = x + (size_t)b * DT + t;

        // x duplicated per-d: xb[d] = {x_d, x_d}; xn = serial round(mul)+add ascending
        ull xb[Dc];
        float xn = 0.f;
        #pragma unroll
        for (int d = 0; d < Dc; d++) {
            const float v = xp[(size_t)d * Tc];
            xn = __fadd_rn(xn, __fmul_rn(v, v));
            asm("mov.b64 %0, {%1, %1};" : "=l"(xb[d]) : "f"(v));
        }

        float best = 3.4e38f;
        int besti = 0;

        // ---- 64 groups of 4 codeword-pairs; each f32x2 lane is a SERIAL fp32
        //      fma chain over d=0..63 ascending (bit-matches cublas SGEMM K-loop) ----
        #pragma unroll 1
        for (int pg = 0; pg < NPAIR / 4; pg++) {
            const unsigned int r0 = pcb_addr + (unsigned)(pg * 4) * (Dc * 8);
            ull a0 = 0ull, a1 = 0ull, a2 = 0ull, a3 = 0ull;

            #pragma unroll
            for (int g = 0; g < Dc / 2; g++) {   // two d-steps per 16B load
                ull c00, c01, c10, c11, c20, c21, c30, c31;
                asm("ld.shared.v2.u64 {%0, %1}, [%2];"
                    : "=l"(c00), "=l"(c01) : "r"(r0 + g * 16));
                asm("ld.shared.v2.u64 {%0, %1}, [%2];"
                    : "=l"(c10), "=l"(c11) : "r"(r0 + 512 + g * 16));
                asm("ld.shared.v2.u64 {%0, %1}, [%2];"
                    : "=l"(c20), "=l"(c21) : "r"(r0 + 1024 + g * 16));
                asm("ld.shared.v2.u64 {%0, %1}, [%2];"
                    : "=l"(c30), "=l"(c31) : "r"(r0 + 1536 + g * 16));
                // serial per lane: a = fma(c_d, x_d, a); a = fma(c_{d+1}, x_{d+1}, a)
                asm("fma.rn.f32x2 %0, %1, %2, %0;" : "+l"(a0) : "l"(c00), "l"(xb[2 * g]));
                asm("fma.rn.f32x2 %0, %1, %2, %0;" : "+l"(a1) : "l"(c10), "l"(xb[2 * g]));
                asm("fma.rn.f32x2 %0, %1, %2, %0;" : "+l"(a2) : "l"(c20), "l"(xb[2 * g]));
                asm("fma.rn.f32x2 %0, %1, %2, %0;" : "+l"(a3) : "l"(c30), "l"(xb[2 * g]));
                asm("fma.rn.f32x2 %0, %1, %2, %0;" : "+l"(a0) : "l"(c01), "l"(xb[2 * g + 1]));
                asm("fma.rn.f32x2 %0, %1, %2, %0;" : "+l"(a1) : "l"(c11), "l"(xb[2 * g + 1]));
                asm("fma.rn.f32x2 %0, %1, %2, %0;" : "+l"(a2) : "l"(c21), "l"(xb[2 * g + 1]));
                asm("fma.rn.f32x2 %0, %1, %2, %0;" : "+l"(a3) : "l"(c31), "l"(xb[2 * g + 1]));
            }

            // epilogue: ascending k order, strict < => first-min like jnp.argmin
            ull accs[4] = {a0, a1, a2, a3};
            #pragma unroll
            for (int q = 0; q < 4; q++) {
                float dlo, dhi;
                asm("mov.b64 {%0, %1}, %2;" : "=f"(dlo), "=f"(dhi) : "l"(accs[q]));
                const int k0 = (pg * 4 + q) * 2;
                // s1 = round(xn - 2*dot) (2*dot exact in fma); score = round(s1 + cn)
                float s = __fadd_rn(fmaf(-2.0f, dlo, xn), scn[k0]);
                if (s < best) { best = s; besti = k0; }
                s = __fadd_rn(fmaf(-2.0f, dhi, xn), scn[k0 + 1]);
                if (s < best) { best = s; besti = k0 + 1; }
            }
        }

        // ---- gather codeword besti from pcb (lane besti&1 of pair besti>>1) ----
        const float* qrow = (const float*)(pcb + (besti >> 1) * Dc);
        const int par = besti & 1;
        float* o1 = out + (size_t)b * DT + t;
        float* o2 = o1 + (size_t)Bc * DT;
        #pragma unroll
        for (int d = 0; d < Dc; d++) {
            const float v = qrow[2 * d + par];
            o1[(size_t)d * Tc] = v;
            if (write_second) o2[(size_t)d * Tc] = v;
        }
    }
}

extern "C" void kernel_launch(void* const* d_in, const int* in_sizes, int n_in,
                              void* d_out, int out_size)
{
    const float* x  = (const float*)d_in[0];   // [16, 64, 8192] fp32
    const float* cb = (const float*)d_in[1];   // [512, 64] fp32
    float* out = (float*)d_out;                // 2 x [16,64,8192]

    static int smem_set = 0;
    if (!smem_set) {
        cudaFuncSetAttribute(vq_kernel,
                             cudaFuncAttributeMaxDynamicSharedMemorySize,
                             SMEM_BYTES);
        smem_set = 1;
    }

    const int write_second = (out_size >= 2 * Bc * DT) ? 1 : 0;
    vq_kernel<<<GRID, THREADS, SMEM_BYTES>>>(x, cb, out, write_second);
}

// round 4
// speedup vs baseline: 1.4331x; 1.4331x over previous
#include <cuda_runtime.h>

// Problem constants
#define Bc 16
#define Dc 64
#define Tc 8192
#define Kc 512
#define DT (Dc * Tc)        // 524288
#define BT (Bc * Tc)        // 131072
#define THREADS 256
#define GRID 148
#define TPC (2 * THREADS)   // tokens per CTA pass (2 per thread)

// smem: plain codebook [512][64] fp32 + cn[512]
#define SMEM_BYTES ((Kc * Dc + Kc) * 4)   // 133120 B

typedef unsigned long long ull;

// one dup'd-c FMA2 step: acc chain (serial in d) for both tokens
#define STEP(acc, fsrc, xreg) do {                                          \
    ull c_;                                                                 \
    asm("mov.b64 %0, {%1, %1};" : "=l"(c_) : "f"(fsrc));                    \
    asm("fma.rn.f32x2 %0, %1, %2, %0;" : "+l"(acc) : "l"(c_), "l"(xreg));   \
} while (0)

__global__ __launch_bounds__(THREADS, 1)
void vq_kernel(const float* __restrict__ x,
               const float* __restrict__ cb,
               float* __restrict__ out,
               int write_second)
{
    extern __shared__ float smem[];
    float* scb = smem;             // [512][64] plain row-major
    float* scn = smem + Kc * Dc;   // [512]

    const int tid = threadIdx.x;

    // ---- cooperative codebook load ----
    {
        const float4* s4 = (const float4*)cb;
        float4* d4 = (float4*)scb;
        #pragma unroll
        for (int i = tid; i < (Kc * Dc) / 4; i += THREADS)
            d4[i] = s4[i];
    }
    __syncthreads();
    // ---- cn[k]: serial round(mul)+add ascending d (matches XLA square+reduce) ----
    for (int k = tid; k < Kc; k += THREADS) {
        float s = 0.f;
        #pragma unroll
        for (int d = 0; d < Dc; d++) {
            float c = scb[k * Dc + d];
            s = __fadd_rn(s, __fmul_rn(c, c));
        }
        scn[k] = s;
    }
    __syncthreads();

    unsigned scb_addr;
    asm("{ .reg .u64 tt; cvta.to.shared.u64 tt, %1; cvt.u32.u64 %0, tt; }"
        : "=r"(scb_addr) : "l"(scb));

    ull m2;   // {-2.0f, -2.0f}
    {
        float mm = -2.0f;
        asm("mov.b64 %0, {%1, %1};" : "=l"(m2) : "f"(mm));
    }

    // ---- grid-stride over token batches; thread owns tokens t0 and t0+256 ----
    for (int base = blockIdx.x * TPC; base < BT; base += GRID * TPC) {
        const int b = base >> 13;                  // base multiple of 512 -> same b for both
        const int t0 = (base & (Tc - 1)) + tid;
        const float* xrow = x + (size_t)b * DT;

        // x packed {x_t0[d], x_t1[d]}: 64 u64; xn serial per token
        ull xv[Dc];
        float xn0 = 0.f, xn1 = 0.f;
        #pragma unroll
        for (int d = 0; d < Dc; d++) {
            const float v0 = xrow[(size_t)d * Tc + t0];
            const float v1 = xrow[(size_t)d * Tc + t0 + THREADS];
            xn0 = __fadd_rn(xn0, __fmul_rn(v0, v0));
            xn1 = __fadd_rn(xn1, __fmul_rn(v1, v1));
            asm("mov.b64 %0, {%1, %2};" : "=l"(xv[d]) : "f"(v0), "f"(v1));
        }
        ull xnp;
        asm("mov.b64 %0, {%1, %2};" : "=l"(xnp) : "f"(xn0), "f"(xn1));

        float best0 = 3.4e38f, best1 = 3.4e38f;
        int bi0 = 0, bi1 = 0;

        // ---- 256 blocks of 2 codewords; each lane = one token, serial d chain ----
        #pragma unroll 1
        for (int kb = 0; kb < Kc; kb += 2) {
            const unsigned r0 = scb_addr + (unsigned)kb * (Dc * 4);
            ull a0 = 0ull, a1 = 0ull;

            #pragma unroll
            for (int g = 0; g < 16; g++) {
                float f00, f01, f02, f03, f10, f11, f12, f13;
                asm("ld.shared.v4.f32 {%0,%1,%2,%3}, [%4];"
                    : "=f"(f00), "=f"(f01), "=f"(f02), "=f"(f03)
                    : "r"(r0 + g * 16));
                asm("ld.shared.v4.f32 {%0,%1,%2,%3}, [%4];"
                    : "=f"(f10), "=f"(f11), "=f"(f12), "=f"(f13)
                    : "r"(r0 + 256 + g * 16));
                // interleave the two serial chains (ILP=2 covers FFMA2 lat/rt)
                STEP(a0, f00, xv[4 * g + 0]);
                STEP(a1, f10, xv[4 * g + 0]);
                STEP(a0, f01, xv[4 * g + 1]);
                STEP(a1, f11, xv[4 * g + 1]);
                STEP(a0, f02, xv[4 * g + 2]);
                STEP(a1, f12, xv[4 * g + 2]);
                STEP(a0, f03, xv[4 * g + 3]);
                STEP(a1, f13, xv[4 * g + 3]);
            }

            // s1 = round(-2*dot + xn) per lane; score = round(s1 + cn); ascending k, strict <
            ull s0p, s1p;
            asm("fma.rn.f32x2 %0, %1, %2, %3;" : "=l"(s0p) : "l"(a0), "l"(m2), "l"(xnp));
            asm("fma.rn.f32x2 %0, %1, %2, %3;" : "=l"(s1p) : "l"(a1), "l"(m2), "l"(xnp));
            float p00, p01, p10, p11;
            asm("mov.b64 {%0, %1}, %2;" : "=f"(p00), "=f"(p01) : "l"(s0p));
            asm("mov.b64 {%0, %1}, %2;" : "=f"(p10), "=f"(p11) : "l"(s1p));
            const float cn0 = scn[kb], cn1 = scn[kb + 1];
            float sc;
            sc = __fadd_rn(p00, cn0); if (sc < best0) { best0 = sc; bi0 = kb; }
            sc = __fadd_rn(p10, cn1); if (sc < best0) { best0 = sc; bi0 = kb + 1; }
            sc = __fadd_rn(p01, cn0); if (sc < best1) { best1 = sc; bi1 = kb; }
            sc = __fadd_rn(p11, cn1); if (sc < best1) { best1 = sc; bi1 = kb + 1; }
        }

        // ---- gather + write both tokens, both outputs ----
        float* o0 = out + (size_t)b * DT + t0;
        float* o1 = o0 + THREADS;
        const float4* q0 = (const float4*)(scb + bi0 * Dc);
        const float4* q1 = (const float4*)(scb + bi1 * Dc);
        #pragma unroll
        for (int g = 0; g < 16; g++) {
            const float4 qa = q0[g];
            const float4 qb = q1[g];
            const size_t r0o = (size_t)(4 * g) * Tc;
            o0[r0o] = qa.x; o0[r0o + Tc] = qa.y; o0[r0o + 2 * Tc] = qa.z; o0[r0o + 3 * Tc] = qa.w;
            o1[r0o] = qb.x; o1[r0o + Tc] = qb.y; o1[r0o + 2 * Tc] = qb.z; o1[r0o + 3 * Tc] = qb.w;
            if (write_second) {
                float* p0 = o0 + (size_t)Bc * DT;
                float* p1 = o1 + (size_t)Bc * DT;
                p0[r0o] = qa.x; p0[r0o + Tc] = qa.y; p0[r0o + 2 * Tc] = qa.z; p0[r0o + 3 * Tc] = qa.w;
                p1[r0o] = qb.x; p1[r0o + Tc] = qb.y; p1[r0o + 2 * Tc] = qb.z; p1[r0o + 3 * Tc] = qb.w;
            }
        }
    }
}

extern "C" void kernel_launch(void* const* d_in, const int* in_sizes, int n_in,
                              void* d_out, int out_size)
{
    const float* x  = (const float*)d_in[0];   // [16, 64, 8192] fp32
    const float* cb = (const float*)d_in[1];   // [512, 64] fp32
    float* out = (float*)d_out;                // 2 x [16,64,8192]

    static int smem_set = 0;
    if (!smem_set) {
        cudaFuncSetAttribute(vq_kernel,
                             cudaFuncAttributeMaxDynamicSharedMemorySize,
                             SMEM_BYTES);
        smem_set = 1;
    }

    const int write_second = (out_size >= 2 * Bc * DT) ? 1 : 0;
    vq_kernel<<<GRID, THREADS, SMEM_BYTES>>>(x, cb, out, write_second);
}